// round 4
// baseline (speedup 1.0000x reference)
#include <cuda_runtime.h>
#include <math.h>

#define LTOT    19530
#define BB      64
#define SS      32
#define NROWS   2048
#define NBISECT 40
#define THREADS 512
#define SMEM_BYTES (LTOT * 4)   // 78120 B per block (dynamic)

// ---------------------------------------------------------------------------
// Kernel 0: zero the output (it is poisoned before timing; we accumulate into it)
// ---------------------------------------------------------------------------
__global__ __launch_bounds__(256) void k_zero(float4* __restrict__ out) {
    const int i = blockIdx.x * 256 + threadIdx.x;
    if (i < (BB * LTOT) / 4) out[i] = make_float4(0.f, 0.f, 0.f, 0.f);
}

// ---------------------------------------------------------------------------
// Kernel 1: fused single-pass — per-row: load to smem, level sums, bisection,
// scale, atomic accumulate into out[b]. One block per (b,s) row.
// ---------------------------------------------------------------------------
__device__ __forceinline__ int level_of(int idx) {
    if (idx < 5)    return 1;
    if (idx < 30)   return 2;
    if (idx < 155)  return 3;
    if (idx < 780)  return 4;
    if (idx < 3905) return 5;
    return 6;
}

__global__ __launch_bounds__(THREADS, 2) void k_fused(const float* __restrict__ sig,
                                                      float* __restrict__ out) {
    extern __shared__ float srow[];               // LTOT floats
    const int row = blockIdx.x;                   // b*32 + s
    const int tid = threadIdx.x;
    const int b   = row >> 5;
    const float* __restrict__ x = sig + (size_t)row * LTOT;

    // ---- Phase 1: stream row into smem (the only DRAM read) ----
    // Row byte base = row*78120; 78120 % 16 == 8 -> float4 phase 0 (even row) or 2 (odd).
    const int a  = (row & 1) ? 2 : 0;
    if (tid < a) srow[tid] = x[tid];
    const int nv = (LTOT - a) >> 2;               // 4882
    const float4* __restrict__ xv = (const float4*)(x + a);
    if (a == 0) {
        float4* sv = (float4*)srow;
        #pragma unroll 8
        for (int i = tid; i < nv; i += THREADS) sv[i] = xv[i];
    } else {
        #pragma unroll 8
        for (int i = tid; i < nv; i += THREADS) {
            const float4 v = xv[i];
            float2* p = (float2*)(srow + a + 4 * i);   // 8B-aligned
            p[0] = make_float2(v.x, v.y);
            p[1] = make_float2(v.z, v.w);
        }
    }
    for (int i = a + 4 * nv + tid; i < LTOT; i += THREADS) srow[i] = x[i];
    __syncthreads();

    // ---- Phase 2: per-level squared sums from smem ----
    float acc[6] = {0.f, 0.f, 0.f, 0.f, 0.f, 0.f};
    {
        const int off[5] = {0, 5, 30, 155, 780};
        #pragma unroll
        for (int k = 0; k < 4; k++)
            for (int i = off[k] + tid; i < off[k + 1]; i += THREADS) {
                const float v = srow[i];
                acc[k] = fmaf(v, v, acc[k]);
            }
        // level 5: [780,3905) = 1562 float2 pairs + scalar 3904
        for (int i = tid; i < 1562; i += THREADS) {
            const float2 v = *(const float2*)(srow + 780 + 2 * i);
            acc[4] = fmaf(v.x, v.x, fmaf(v.y, v.y, acc[4]));
        }
        // level 6: scalar 3905 + [3906,19530) = 7812 float2 pairs
        if (tid == 0) {
            float v = srow[3904]; acc[4] = fmaf(v, v, acc[4]);
            v = srow[3905];       acc[5] = fmaf(v, v, acc[5]);
        }
        #pragma unroll 4
        for (int i = tid; i < 7812; i += THREADS) {
            const float2 v = *(const float2*)(srow + 3906 + 2 * i);
            acc[5] = fmaf(v.x, v.x, fmaf(v.y, v.y, acc[5]));
        }
    }

    // ---- Phase 3: block reduce 6 sums ----
    __shared__ float sm[16][8];
    __shared__ float tot[8];
    const int lane = tid & 31, w = tid >> 5;
    #pragma unroll
    for (int k = 0; k < 6; k++) {
        float v = acc[k];
        #pragma unroll
        for (int o = 16; o > 0; o >>= 1) v += __shfl_down_sync(0xffffffffu, v, o);
        if (lane == 0) sm[w][k] = v;
    }
    __syncthreads();
    if (w == 0 && lane < 6) {
        float t = 0.f;
        #pragma unroll
        for (int i = 0; i < 16; i++) t += sm[i][lane];
        tot[lane] = t;
    }
    __syncthreads();

    // ---- Phase 4: bisection (all threads redundantly; same result, no divergence) ----
    float c[7];
    {
        float total = 0.f;
        #pragma unroll
        for (int k = 1; k <= 6; k++) { c[k] = tot[k - 1]; total += c[k]; }
        const float nq  = 1.f + total;                       // phi: C=4, a=1
        const float phi = (nq > 4.f) ? (8.f - 16.f / nq) : nq;
        c[0] = 1.f - phi;
    }
    bool fin = true;
    #pragma unroll
    for (int k = 0; k < 7; k++) fin = fin && isfinite(c[k]);

    float lo = 0.f, hi = 2.f;
    #pragma unroll 4
    for (int it = 0; it < NBISECT; it++) {
        const float mid = 0.5f * (lo + hi);
        const float u   = mid * mid;
        float p = c[6];
        #pragma unroll
        for (int k = 5; k >= 0; k--) p = fmaf(p, u, c[k]);
        const bool neg = p < 0.f;
        lo = neg ? mid : lo;
        hi = neg ? hi  : mid;
    }
    float root = 0.5f * (lo + hi);
    if (!fin) root = 0.f;
    root = fminf(root, 1.f);

    float pw[7];                                   // pw[k] = root^k / 32
    pw[0] = 1.f / 32.f;
    #pragma unroll
    for (int k = 1; k <= 6; k++) pw[k] = pw[k - 1] * root;

    // ---- Phase 5: scale from smem + atomic accumulate into out[b] ----
    float* __restrict__ ob = out + (size_t)b * LTOT;

    // scalars: [0,780) and boundary elements 3904 (lv5), 3905 (lv6)
    for (int i = tid; i < 782; i += THREADS) {
        const int idx = (i < 780) ? i : (3904 + (i - 780));
        atomicAdd(ob + idx, srow[idx] * pw[level_of(idx)]);
    }
    // level-5 pairs [780, 3904)
    {
        const float w5 = pw[5];
        for (int i = tid; i < 1562; i += THREADS) {
            const int idx = 780 + 2 * i;
            const float2 v = *(const float2*)(srow + idx);
            atomicAdd((float2*)(ob + idx), make_float2(v.x * w5, v.y * w5));
        }
    }
    // level-6 pairs [3906, 19530)
    {
        const float w6 = pw[6];
        #pragma unroll 4
        for (int i = tid; i < 7812; i += THREADS) {
            const int idx = 3906 + 2 * i;
            const float2 v = *(const float2*)(srow + idx);
            atomicAdd((float2*)(ob + idx), make_float2(v.x * w6, v.y * w6));
        }
    }
}

// ---------------------------------------------------------------------------
extern "C" void kernel_launch(void* const* d_in, const int* in_sizes, int n_in,
                              void* d_out, int out_size) {
    const float* sig = (const float*)d_in[0];
    float* out = (float*)d_out;

    cudaFuncSetAttribute(k_fused, cudaFuncAttributeMaxDynamicSharedMemorySize, SMEM_BYTES);

    k_zero<<<((BB * LTOT) / 4 + 255) / 256, 256>>>((float4*)out);
    k_fused<<<NROWS, THREADS, SMEM_BYTES>>>(sig, out);
}

// round 5
// speedup vs baseline: 1.2175x; 1.2175x over previous
#include <cuda_runtime.h>
#include <math.h>

#define LTOT    19530
#define BB      64
#define SS      32
#define NROWS   2048
#define NBISECT 40
#define N4      4882        // full float4-column groups per row (4*4882 = 19528)

// Scratch (__device__ global: allocation-guard compliant)
__device__ float g_pw[NROWS * 8];   // per-row root powers [row][k] = root^k

// ---------------------------------------------------------------------------
// Kernel 1: per-row per-level squared sums (vectorized) + fused bisection
// ---------------------------------------------------------------------------
__device__ __forceinline__ void vec_sq_sum(const float* __restrict__ x,
                                           int lo, int hi, int p,
                                           int tid, float& acc) {
    int a = lo + ((((p - lo) % 4) + 4) % 4);      // first idx >= lo with idx%4==p
    if (tid < a - lo) { float v = x[lo + tid]; acc = fmaf(v, v, acc); }
    const int nv = (hi - a) >> 2;
    const float4* __restrict__ xv = (const float4*)(x + a);
    #pragma unroll 4
    for (int i = tid; i < nv; i += 256) {
        float4 v = xv[i];
        acc = fmaf(v.x, v.x, acc);
        acc = fmaf(v.y, v.y, acc);
        acc = fmaf(v.z, v.z, acc);
        acc = fmaf(v.w, v.w, acc);
    }
    const int t0 = a + 4 * nv;
    if (tid < hi - t0) { float v = x[t0 + tid]; acc = fmaf(v, v, acc); }
}

__global__ __launch_bounds__(256) void k_levelsums(const float* __restrict__ sig) {
    const int row = blockIdx.x;
    const int tid = threadIdx.x;
    const float* __restrict__ x = sig + (size_t)row * LTOT;

    float acc[6] = {0.f, 0.f, 0.f, 0.f, 0.f, 0.f};

    const int off[5] = {0, 5, 30, 155, 780};
    #pragma unroll
    for (int k = 0; k < 4; k++)
        for (int i = off[k] + tid; i < off[k + 1]; i += 256) {
            float v = x[i];
            acc[k] = fmaf(v, v, acc[k]);
        }

    // Row byte base = row*78120; 78120 % 16 == 8 -> float4 phase 0 (even) / 2 (odd)
    const int p = (row & 1) ? 2 : 0;
    vec_sq_sum(x, 780,  3905, p, tid, acc[4]);
    vec_sq_sum(x, 3905, LTOT, p, tid, acc[5]);

    __shared__ float sm[8][8];
    __shared__ float totals[8];
    const int lane = tid & 31, w = tid >> 5;
    #pragma unroll
    for (int k = 0; k < 6; k++) {
        float v = acc[k];
        #pragma unroll
        for (int o = 16; o > 0; o >>= 1) v += __shfl_down_sync(0xffffffffu, v, o);
        if (lane == 0) sm[w][k] = v;
    }
    __syncthreads();
    if (w == 0) {
        if (lane < 6) {
            float t = 0.f;
            #pragma unroll
            for (int i = 0; i < 8; i++) t += sm[i][lane];
            totals[lane] = t;
        }
        __syncwarp();
        if (lane == 0) {
            // phi: C=4, a=1 -> phi(x) = 8 - 16/x for x > 4
            float c[7];
            float total = 0.f;
            #pragma unroll
            for (int k = 1; k <= 6; k++) { c[k] = totals[k - 1]; total += c[k]; }
            const float nq  = 1.f + total;
            const float phi = (nq > 4.f) ? (8.f - 16.f / nq) : nq;
            c[0] = 1.f - phi;

            bool fin = true;
            #pragma unroll
            for (int k = 0; k < 7; k++) fin = fin && isfinite(c[k]);

            float lo = 0.f, hi = 2.f;
            #pragma unroll 4
            for (int it = 0; it < NBISECT; it++) {
                const float mid = 0.5f * (lo + hi);
                const float u   = mid * mid;
                float pz = c[6];
                #pragma unroll
                for (int k = 5; k >= 0; k--) pz = fmaf(pz, u, c[k]);
                const bool neg = pz < 0.f;
                lo = neg ? mid : lo;
                hi = neg ? hi  : mid;
            }
            float root = 0.5f * (lo + hi);
            if (!fin) root = 0.f;
            root = fminf(root, 1.f);

            float pw = 1.f;
            g_pw[row * 8 + 0] = 1.f;
            #pragma unroll
            for (int k = 1; k <= 6; k++) { pw *= root; g_pw[row * 8 + k] = pw; }
            g_pw[row * 8 + 7] = 0.f;
        }
    }
}

// ---------------------------------------------------------------------------
// Kernel 2: scale by root^level, mean over S. 4 columns/thread, explicit
// 8-sample load batches (16 x LDG.64 front-batched) for MLP.
// ---------------------------------------------------------------------------
__device__ __forceinline__ int level_of(int idx) {
    if (idx < 5)    return 1;
    if (idx < 30)   return 2;
    if (idx < 155)  return 3;
    if (idx < 780)  return 4;
    if (idx < 3905) return 5;
    return 6;
}

__global__ __launch_bounds__(256, 4) void k_scale(const float* __restrict__ sig,
                                                  float* __restrict__ out) {
    const int b = blockIdx.y;

    __shared__ float spw[SS * 8];
    spw[threadIdx.x] = g_pw[(size_t)b * SS * 8 + threadIdx.x];
    __syncthreads();

    const int j4 = blockIdx.x * 256 + threadIdx.x;
    if (j4 > N4) return;

    const float* __restrict__ base = sig + (size_t)b * SS * LTOT;
    const float inv = 1.f / (float)SS;

    if (j4 < N4) {
        const int e0 = 4 * j4;
        const int lv0 = level_of(e0);
        const int lv1 = level_of(e0 + 1);
        const int lv2 = level_of(e0 + 2);
        const int lv3 = level_of(e0 + 3);

        float a0 = 0.f, a1 = 0.f, a2 = 0.f, a3 = 0.f;

        #pragma unroll
        for (int sb = 0; sb < SS; sb += 8) {
            // ---- load batch: 16 x LDG.64 issued before any consumption ----
            float2 u[16];
            #pragma unroll
            for (int t = 0; t < 8; t++) {
                const float* r = base + (size_t)(sb + t) * LTOT + e0;  // 8B aligned
                u[2 * t]     = *(const float2*)r;
                u[2 * t + 1] = *(const float2*)(r + 2);
            }
            // ---- consume ----
            #pragma unroll
            for (int t = 0; t < 8; t++) {
                const int s = sb + t;
                a0 = fmaf(u[2 * t].x,     spw[s * 8 + lv0], a0);
                a1 = fmaf(u[2 * t].y,     spw[s * 8 + lv1], a1);
                a2 = fmaf(u[2 * t + 1].x, spw[s * 8 + lv2], a2);
                a3 = fmaf(u[2 * t + 1].y, spw[s * 8 + lv3], a3);
            }
        }
        float* o = out + (size_t)b * LTOT + e0;     // 8B aligned
        *(float2*)o       = make_float2(a0 * inv, a1 * inv);
        *(float2*)(o + 2) = make_float2(a2 * inv, a3 * inv);
    } else {
        // tail: elements 19528, 19529 (level 6)
        const int e0 = 4 * N4;
        float a0 = 0.f, a1 = 0.f;
        #pragma unroll 8
        for (int s = 0; s < SS; s++) {
            const float2 v = *(const float2*)(base + (size_t)s * LTOT + e0);
            const float  w = spw[s * 8 + 6];
            a0 = fmaf(v.x, w, a0);
            a1 = fmaf(v.y, w, a1);
        }
        float* o = out + (size_t)b * LTOT + e0;
        *(float2*)o = make_float2(a0 * inv, a1 * inv);
    }
}

// ---------------------------------------------------------------------------
extern "C" void kernel_launch(void* const* d_in, const int* in_sizes, int n_in,
                              void* d_out, int out_size) {
    const float* sig = (const float*)d_in[0];
    float* out = (float*)d_out;

    k_levelsums<<<NROWS, 256>>>(sig);
    dim3 g2((N4 + 1 + 255) / 256, BB);   // 20 x 64 blocks
    k_scale<<<g2, 256>>>(sig, out);
}